// round 14
// baseline (speedup 1.0000x reference)
#include <cuda_runtime.h>
#include <cuda_bf16.h>
#include <cstdint>
#include <cstddef>

#define BB 2048
#define SS 8
#define NN 4096
#define HH 256
#define SH 2048
#define KCAP 512
#define TAU 9.094947017729282e-13f   // 2^-40

// ------------- static scratch -------------
__device__ float d_g[SS * NN];
__device__ float d_Zinv[BB * SS];
__device__ float d_Wvo[HH * HH];
__device__ float d_bconst[HH];
__device__ float d_cvec[SS * HH];
__device__ float d_e2[BB * SS];
__device__ int   d_idx[SS * KCAP];
__device__ int   d_cnt[SS];
__device__ __align__(128) __nv_bfloat16 d_Asp[(size_t)SS * BB * KCAP];   // 16MB
__device__ __align__(128) __nv_bfloat16 d_Bsph[(size_t)SS * HH * KCAP]; // 2MB
__device__ __align__(128) __nv_bfloat16 d_Bspl[(size_t)SS * HH * KCAP]; // 2MB
__device__ __align__(128) __nv_bfloat16 d_Mth[SS * HH * HH];
__device__ __align__(128) __nv_bfloat16 d_Mtl[SS * HH * HH];
__device__ __align__(128) __nv_bfloat16 d_W1h[HH * HH];
__device__ __align__(128) __nv_bfloat16 d_W1l[HH * HH];
__device__ __align__(128) __nv_bfloat16 d_bssh[(size_t)BB * SH];   // 8MB
__device__ __align__(128) __nv_bfloat16 d_bssl[(size_t)BB * SH];   // 8MB

__device__ __forceinline__ uint32_t smem_u32(const void* p) {
    uint32_t a;
    asm("{ .reg .u64 t; cvta.to.shared.u64 t, %1; cvt.u32.u64 %0, t; }" : "=r"(a) : "l"(p));
    return a;
}

#define LDMX4(r, addr)                                                         \
    asm volatile("ldmatrix.sync.aligned.m8n8.x4.shared.b16 {%0,%1,%2,%3}, [%4];" \
        : "=r"((r)[0]), "=r"((r)[1]), "=r"((r)[2]), "=r"((r)[3]) : "r"(addr))

#define MMA16816(d, a, b0, b1)                                                 \
    asm volatile("mma.sync.aligned.m16n8k16.row.col.f32.bf16.bf16.f32 "        \
        "{%0,%1,%2,%3},{%4,%5,%6,%7},{%8,%9},{%0,%1,%2,%3};"                   \
        : "+f"((d)[0]), "+f"((d)[1]), "+f"((d)[2]), "+f"((d)[3])               \
        : "r"((a)[0]), "r"((a)[1]), "r"((a)[2]), "r"((a)[3]), "r"(b0), "r"(b1))

#define CP16(saddr, gptr)                                                      \
    asm volatile("cp.async.cg.shared.global [%0], [%1], 16;"                   \
        :: "r"(saddr), "l"(gptr) : "memory")

__device__ __forceinline__ uint32_t pack_hi(float a, float b) {
    __nv_bfloat162 p;
    p.x = __float2bfloat16(a); p.y = __float2bfloat16(b);
    return *(uint32_t*)&p;
}
__device__ __forceinline__ uint32_t pack_lo(float a, float b) {
    __nv_bfloat162 p;
    p.x = __float2bfloat16(a - __bfloat162float(__float2bfloat16(a)));
    p.y = __float2bfloat16(b - __bfloat162float(__float2bfloat16(b)));
    return *(uint32_t*)&p;
}

// ------------- K1: scores -------------
__global__ void k_scores(const float* __restrict__ E, const float* __restrict__ att) {
    __shared__ float satt[HH];
    int tid = threadIdx.x;
    satt[tid] = att[tid];
    __syncthreads();
    int w = tid >> 5, lane = tid & 31;
    int s = blockIdx.x >> 9;
    int n = ((blockIdx.x & 511) << 3) + w;
    const float* e = E + ((size_t)s * NN + n) * HH + lane * 8;
    const float* a = satt + lane * 8;
    float4 v0 = *(const float4*)e, v1 = *(const float4*)(e + 4);
    float4 a0 = *(const float4*)a, a1 = *(const float4*)(a + 4);
    float acc = v0.x*a0.x + v0.y*a0.y + v0.z*a0.z + v0.w*a0.w
              + v1.x*a1.x + v1.y*a1.y + v1.z*a1.z + v1.w*a1.w;
    #pragma unroll
    for (int o = 16; o; o >>= 1) acc += __shfl_xor_sync(0xffffffffu, acc, o);
    if (lane == 0) d_g[s * NN + n] = acc;
}

// ------------- K2: max + exp + select (one CTA per s) -------------
__global__ void k_expsel() {
    int s = blockIdx.x, tid = threadIdx.x;
    int lane = tid & 31, wid = tid >> 5;
    __shared__ float wmax[8];
    __shared__ int wtot[8], woff[8], stot;
    int base = tid * 16;
    float sc[16];
    float mx = -1e30f;
    #pragma unroll
    for (int j = 0; j < 16; j++) {
        sc[j] = d_g[s * NN + base + j];
        mx = fmaxf(mx, sc[j]);
    }
    #pragma unroll
    for (int o = 16; o; o >>= 1) mx = fmaxf(mx, __shfl_xor_sync(0xffffffffu, mx, o));
    if (lane == 0) wmax[wid] = mx;
    __syncthreads();
    float gmx = wmax[0];
    #pragma unroll
    for (int i = 1; i < 8; i++) gmx = fmaxf(gmx, wmax[i]);

    float gv[16];
    int c = 0;
    #pragma unroll
    for (int j = 0; j < 16; j++) {
        gv[j] = expf(sc[j] - gmx);
        d_g[s * NN + base + j] = gv[j];
        c += (gv[j] >= TAU) ? 1 : 0;
    }
    int v = c;
    #pragma unroll
    for (int o = 1; o < 32; o <<= 1) {
        int t = __shfl_up_sync(0xffffffffu, v, o);
        if (lane >= o) v += t;
    }
    if (lane == 31) wtot[wid] = v;
    __syncthreads();
    if (tid == 0) {
        int a = 0;
        #pragma unroll
        for (int i = 0; i < 8; i++) { woff[i] = a; a += wtot[i]; }
        stot = a;
    }
    __syncthreads();
    int o = woff[wid] + v - c;
    #pragma unroll
    for (int j = 0; j < 16; j++) {
        if (gv[j] >= TAU) {
            if (o < KCAP) d_idx[s * KCAP + o] = base + j;
            o++;
        }
    }
    int total = stot < KCAP ? stot : KCAP;
    if (tid == 0) d_cnt[s] = total;
    for (int k = total + tid; k < KCAP; k += 256) d_idx[s * KCAP + k] = 0;
}

// ------------- K3: Asp + sparse Zinv. One CTA per b; DM row cached in smem ---
__global__ void k_prepAspZ(const int* __restrict__ DM) {
    int b = blockIdx.x, tid = threadIdx.x;
    int lane = tid & 31, wid = tid >> 5;
    __shared__ int sdm[NN];              // 16 KB dense DM row
    __shared__ float wpart[SS][8];
    const int4* src = (const int4*)(DM + (size_t)b * NN);
    int4* dst = (int4*)sdm;
    for (int i = tid; i < NN / 4; i += 256) dst[i] = src[i];
    __syncthreads();

    float z[SS];
    #pragma unroll
    for (int s = 0; s < SS; s++) z[s] = 0.f;
    #pragma unroll
    for (int s = 0; s < SS; s++) {
        int cnt = d_cnt[s];
        int lim = (cnt + 31) & ~31;
        for (int k = tid; k < lim; k += 256) {
            int n = d_idx[s * KCAP + k];
            float v = (k < cnt) ? (float)sdm[n] : 0.f;
            d_Asp[((size_t)s * BB + b) * KCAP + k] = __float2bfloat16(v);
            z[s] += v * d_g[s * NN + n];
        }
    }
    #pragma unroll
    for (int s = 0; s < SS; s++) {
        float t = z[s];
        #pragma unroll
        for (int o = 16; o; o >>= 1) t += __shfl_xor_sync(0xffffffffu, t, o);
        if (lane == 0) wpart[s][wid] = t;
    }
    __syncthreads();
    if (tid < SS) {
        float t = 0.f;
        #pragma unroll
        for (int w = 0; w < 8; w++) t += wpart[tid][w];
        d_Zinv[b * SS + tid] = 1.f / t;
    }
}

// ------------- K4: Bsp[s][h][k] = hi/lo of g*E at idx_k -------------
__global__ void k_prepBsp(const float* __restrict__ E) {
    int s = blockIdx.x, kt = blockIdx.y, tid = threadIdx.x;
    int cnt = d_cnt[s];
    if (kt * 32 >= ((cnt + 31) & ~31)) return;
    __shared__ float tile[32][257];
    for (int r = 0; r < 32; r++) {
        int k = kt * 32 + r;
        int n = d_idx[s * KCAP + k];
        float gv = (k < cnt) ? d_g[s * NN + n] : 0.f;
        tile[r][tid] = gv * E[((size_t)s * NN + n) * HH + tid];
    }
    __syncthreads();
    int h = tid;
    #pragma unroll
    for (int r = 0; r < 32; r += 2) {
        size_t o = ((size_t)s * HH + h) * KCAP + kt * 32 + r;
        *(uint32_t*)(d_Bsph + o) = pack_hi(tile[r][h], tile[r + 1][h]);
        *(uint32_t*)(d_Bspl + o) = pack_lo(tile[r][h], tile[r + 1][h]);
    }
}

// ------------- K5: Wvo / bconst -------------
__global__ void k_wvo(const float* __restrict__ Wo, const float* __restrict__ Wv,
                      const float* __restrict__ bv, const float* __restrict__ bo) {
    int g = blockIdx.x, tid = threadIdx.x;
    __shared__ float srow[HH];
    __shared__ float red[HH];
    srow[tid] = Wo[g * HH + tid];
    __syncthreads();
    float acc = 0.f;
    #pragma unroll 4
    for (int k = 0; k < HH; k++) acc += srow[k] * Wv[k * HH + tid];
    d_Wvo[g * HH + tid] = acc;
    red[tid] = srow[tid] * bv[tid];
    __syncthreads();
    for (int o = 128; o; o >>= 1) {
        if (tid < o) red[tid] += red[tid + o];
        __syncthreads();
    }
    if (tid == 0) d_bconst[g] = red[0] + bo[g];
}

// ------------- K6: Mtb[s][g][h] = ((I+L_s)@Wvo)[g,h], bf16 hi/lo -------------
__global__ void k_M(const float* __restrict__ LW) {
    int s = blockIdx.x, gt = blockIdx.y;
    int h = threadIdx.x;
    __shared__ float sL[32][HH];
    for (int g = 0; g < 32; g++)
        sL[g][h] = LW[((size_t)s * HH + gt * 32 + g) * HH + h];
    __syncthreads();
    float acc[32];
    #pragma unroll
    for (int g = 0; g < 32; g++) acc[g] = d_Wvo[(gt * 32 + g) * HH + h];
    #pragma unroll 4
    for (int k = 0; k < HH; k++) {
        float wv = d_Wvo[k * HH + h];
        #pragma unroll
        for (int g = 0; g < 32; g++) acc[g] += sL[g][k] * wv;
    }
    for (int g = 0; g < 32; g++) {
        float v = acc[g];
        __nv_bfloat16 hi = __float2bfloat16(v);
        __nv_bfloat16 lo = __float2bfloat16(v - __bfloat162float(hi));
        size_t o = (size_t)(s * HH + gt * 32 + g) * HH + h;
        d_Mth[o] = hi;
        d_Mtl[o] = lo;
    }
}

// ------------- K7: cvec -------------
__global__ void k_cvec(const float* __restrict__ LW, const float* __restrict__ LB) {
    int s = blockIdx.x, g = threadIdx.x;
    __shared__ float sb[HH];
    sb[g] = d_bconst[g];
    __syncthreads();
    float acc = 0.f;
    #pragma unroll 4
    for (int k = 0; k < HH; k++) acc += LW[((size_t)s * HH + g) * HH + k] * sb[k];
    d_cvec[s * HH + g] = d_bconst[g] + acc + LB[s * HH + g];
}

// ------------- K8: W1 -> bf16 hi/lo -------------
__global__ void k_w1c(const float* __restrict__ W1) {
    int i = blockIdx.x * 256 + threadIdx.x;
    float v = W1[i];
    __nv_bfloat16 hi = __float2bfloat16(v);
    d_W1h[i] = hi;
    d_W1l[i] = __float2bfloat16(v - __bfloat162float(hi));
}

// ====================================================================
// MEGA kernel: CTA = (s, 128 b-rows). Grid (8, 16).
// Phase 1: sparse numerator GEMM -> scaled bsym hi/lo into smem planes
// Phase 2: bsym @ Mt^T (3-pass) + cvec -> bssh/bssl global + planes
// Phase 3: bss @ W1^T (3-pass) -> tanh-reduce -> d_e2
// Depth-1 double buffer; epilogue 2 recomputes packs (no reg staging).
// ====================================================================
#define BK 32
#define STG 40960
#define PSTR 528
#define PLH 81920
#define PLL 149504
#define SMEM_MEGA 217088

__global__ __launch_bounds__(256, 1) void k_mega(
    const float* __restrict__ B1, const float* __restrict__ W2)
{
    extern __shared__ char smem[];
    const int tid = threadIdx.x, wid = tid >> 5, lane = tid & 31;
    const int warp_m = wid & 1, warp_n = wid >> 1;
    const int s = blockIdx.x, mBase = blockIdx.y * 128;
    const uint32_t sb = smem_u32(smem);

    const int cRow = tid >> 2, cSeg = tid & 3;
    const uint32_t aOfs1 = (warp_m * 64 + (lane & 15)) * 80 + (lane >> 4) * 16;
    const uint32_t bRowF = warp_n * 64 + (lane & 7) + ((lane >> 4) << 3);
    const uint32_t bFr = bRowF * 80 + ((lane >> 3) & 1) * 16;
    const uint32_t aPRow = (warp_m * 64 + (lane & 15)) * PSTR + (lane >> 4) * 16;

    float acc[4][8][4];

    // =================== PHASE 1: sparse numerator ===================
    {
        const __nv_bfloat16* aC = d_Asp  + ((size_t)s * BB + mBase) * KCAP;
        const __nv_bfloat16* bH = d_Bsph + (size_t)s * HH * KCAP;
        const __nv_bfloat16* bL = d_Bspl + (size_t)s * HH * KCAP;
        const int cnt = d_cnt[s];
        const int nch = (cnt + 31) >> 5;
        const int NT = 2 * nch;

        #pragma unroll
        for (int fm = 0; fm < 4; fm++)
            #pragma unroll
            for (int fn = 0; fn < 8; fn++)
                #pragma unroll
                for (int q = 0; q < 4; q++) acc[fm][fn][q] = 0.f;

        auto issue1 = [&](int kt) {
            uint32_t s0 = sb + (kt & 1) * STG;
            int kk = (kt < nch) ? kt : kt - nch;
            const __nv_bfloat16* bp = (kt < nch) ? bH : bL;
            #pragma unroll
            for (int i = 0; i < 2; i++) {
                int row = cRow + i * 64;
                CP16(s0 + row * 80 + cSeg * 16, aC + (size_t)row * KCAP + kk * BK + cSeg * 8);
            }
            #pragma unroll
            for (int i = 0; i < 4; i++) {
                int row = cRow + i * 64;
                CP16(s0 + 10240 + row * 80 + cSeg * 16, bp + (size_t)row * KCAP + kk * BK + cSeg * 8);
            }
            asm volatile("cp.async.commit_group;" ::: "memory");
        };

        issue1(0);
        for (int kt = 0; kt < NT; kt++) {
            asm volatile("cp.async.wait_group 0;" ::: "memory");
            __syncthreads();
            if (kt + 1 < NT) issue1(kt + 1);
            uint32_t sA = sb + (kt & 1) * STG;
            #pragma unroll
            for (int ks = 0; ks < 2; ks++) {
                uint32_t aF[4][4], bF[4][4];
                #pragma unroll
                for (int fm = 0; fm < 4; fm++)
                    LDMX4(aF[fm], sA + aOfs1 + fm * (16 * 80) + ks * 32);
                #pragma unroll
                for (int fb = 0; fb < 4; fb++)
                    LDMX4(bF[fb], sA + 10240 + bFr + fb * (16 * 80) + ks * 32);
                #pragma unroll
                for (int fm = 0; fm < 4; fm++)
                    #pragma unroll
                    for (int fn = 0; fn < 8; fn++)
                        MMA16816(acc[fm][fn], aF[fm],
                                 bF[fn >> 1][(fn & 1) * 2], bF[fn >> 1][(fn & 1) * 2 + 1]);
            }
        }

        // epilogue 1: scale by Zinv, write hi/lo into smem planes
        __syncthreads();
        #pragma unroll
        for (int fm = 0; fm < 4; fm++) {
            int rl = warp_m * 64 + fm * 16 + (lane >> 2);
            float zi0 = d_Zinv[(mBase + rl) * SS + s];
            float zi1 = d_Zinv[(mBase + rl + 8) * SS + s];
            #pragma unroll
            for (int fn = 0; fn < 8; fn++) {
                int col = warp_n * 64 + fn * 8 + (lane & 3) * 2;
                float v00 = acc[fm][fn][0] * zi0, v01 = acc[fm][fn][1] * zi0;
                float v10 = acc[fm][fn][2] * zi1, v11 = acc[fm][fn][3] * zi1;
                *(uint32_t*)(smem + PLH + rl * PSTR + col * 2)       = pack_hi(v00, v01);
                *(uint32_t*)(smem + PLL + rl * PSTR + col * 2)       = pack_lo(v00, v01);
                *(uint32_t*)(smem + PLH + (rl + 8) * PSTR + col * 2) = pack_hi(v10, v11);
                *(uint32_t*)(smem + PLL + (rl + 8) * PSTR + col * 2) = pack_lo(v10, v11);
            }
        }
    }
    __syncthreads();

    // =================== PHASE 2 & 3 shared mainloop ===================
    auto gemm_planes = [&](const __nv_bfloat16* Bh, const __nv_bfloat16* Bl) {
        #pragma unroll
        for (int fm = 0; fm < 4; fm++)
            #pragma unroll
            for (int fn = 0; fn < 8; fn++)
                #pragma unroll
                for (int q = 0; q < 4; q++) acc[fm][fn][q] = 0.f;

        auto issue2 = [&](int kt) {
            uint32_t s0 = sb + (kt & 1) * STG;
            #pragma unroll
            for (int i = 0; i < 4; i++) {
                int row = cRow + i * 64;
                size_t go = (size_t)row * HH + kt * BK + cSeg * 8;
                CP16(s0 + row * 80 + cSeg * 16, Bh + go);
                CP16(s0 + 20480 + row * 80 + cSeg * 16, Bl + go);
            }
            asm volatile("cp.async.commit_group;" ::: "memory");
        };

        const int NT = HH / BK;   // 8
        issue2(0);
        for (int kt = 0; kt < NT; kt++) {
            asm volatile("cp.async.wait_group 0;" ::: "memory");
            __syncthreads();
            if (kt + 1 < NT) issue2(kt + 1);
            uint32_t sA = sb + (kt & 1) * STG;
            #pragma unroll
            for (int ks = 0; ks < 2; ks++) {
                uint32_t aH[4][4], aL[4][4], bF[4][4];
                uint32_t aCol = kt * 64 + ks * 32;
                #pragma unroll
                for (int fm = 0; fm < 4; fm++) {
                    LDMX4(aH[fm], sb + PLH + aPRow + fm * (16 * PSTR) + aCol);
                    LDMX4(aL[fm], sb + PLL + aPRow + fm * (16 * PSTR) + aCol);
                }
                #pragma unroll
                for (int fb = 0; fb < 4; fb++)
                    LDMX4(bF[fb], sA + bFr + fb * (16 * 80) + ks * 32);
                #pragma unroll
                for (int fm = 0; fm < 4; fm++)
                    #pragma unroll
                    for (int fn = 0; fn < 8; fn++) {
                        MMA16816(acc[fm][fn], aH[fm],
                                 bF[fn >> 1][(fn & 1) * 2], bF[fn >> 1][(fn & 1) * 2 + 1]);
                        MMA16816(acc[fm][fn], aL[fm],
                                 bF[fn >> 1][(fn & 1) * 2], bF[fn >> 1][(fn & 1) * 2 + 1]);
                    }
                #pragma unroll
                for (int fb = 0; fb < 4; fb++)
                    LDMX4(bF[fb], sA + 20480 + bFr + fb * (16 * 80) + ks * 32);
                #pragma unroll
                for (int fm = 0; fm < 4; fm++)
                    #pragma unroll
                    for (int fn = 0; fn < 8; fn++)
                        MMA16816(acc[fm][fn], aH[fm],
                                 bF[fn >> 1][(fn & 1) * 2], bF[fn >> 1][(fn & 1) * 2 + 1]);
            }
        }
    };

    // =================== PHASE 2: bss ===================
    gemm_planes(d_Mth + (size_t)s * HH * HH, d_Mtl + (size_t)s * HH * HH);

    // epilogue 2a: +cvec, write bssh/bssl global (no plane staging regs)
    #pragma unroll
    for (int fm = 0; fm < 4; fm++) {
        int rl = warp_m * 64 + fm * 16 + (lane >> 2);
        #pragma unroll
        for (int fn = 0; fn < 8; fn++) {
            int col = warp_n * 64 + fn * 8 + (lane & 3) * 2;
            float c0 = d_cvec[s * HH + col], c1 = d_cvec[s * HH + col + 1];
            float v00 = acc[fm][fn][0] + c0, v01 = acc[fm][fn][1] + c1;
            float v10 = acc[fm][fn][2] + c0, v11 = acc[fm][fn][3] + c1;
            size_t o0 = (size_t)(mBase + rl) * SH + s * HH + col;
            size_t o1 = (size_t)(mBase + rl + 8) * SH + s * HH + col;
            *(uint32_t*)(d_bssh + o0) = pack_hi(v00, v01);
            *(uint32_t*)(d_bssl + o0) = pack_lo(v00, v01);
            *(uint32_t*)(d_bssh + o1) = pack_hi(v10, v11);
            *(uint32_t*)(d_bssl + o1) = pack_lo(v10, v11);
        }
    }
    __syncthreads();   // all reads of old planes done
    // epilogue 2b: recompute packs from acc (still live), write planes
    #pragma unroll
    for (int fm = 0; fm < 4; fm++) {
        int rl = warp_m * 64 + fm * 16 + (lane >> 2);
        #pragma unroll
        for (int fn = 0; fn < 8; fn++) {
            int col = warp_n * 64 + fn * 8 + (lane & 3) * 2;
            float c0 = d_cvec[s * HH + col], c1 = d_cvec[s * HH + col + 1];
            float v00 = acc[fm][fn][0] + c0, v01 = acc[fm][fn][1] + c1;
            float v10 = acc[fm][fn][2] + c0, v11 = acc[fm][fn][3] + c1;
            *(uint32_t*)(smem + PLH + rl * PSTR + col * 2)       = pack_hi(v00, v01);
            *(uint32_t*)(smem + PLL + rl * PSTR + col * 2)       = pack_lo(v00, v01);
            *(uint32_t*)(smem + PLH + (rl + 8) * PSTR + col * 2) = pack_hi(v10, v11);
            *(uint32_t*)(smem + PLL + (rl + 8) * PSTR + col * 2) = pack_lo(v10, v11);
        }
    }
    __syncthreads();

    // =================== PHASE 3: e2 ===================
    gemm_planes(d_W1h, d_W1l);

    // epilogue 3: tanh-reduce
    __syncthreads();  // stage region now free for sred
    float* sred = (float*)smem;   // [128][4]
    #pragma unroll
    for (int fm = 0; fm < 4; fm++) {
        #pragma unroll
        for (int half = 0; half < 2; half++) {
            float sum = 0.f;
            #pragma unroll
            for (int fn = 0; fn < 8; fn++) {
                int col = warp_n * 64 + fn * 8 + (lane & 3) * 2;
                float v0 = acc[fm][fn][half * 2 + 0];
                float v1 = acc[fm][fn][half * 2 + 1];
                sum += tanhf(v0 + B1[col]) * W2[col]
                     + tanhf(v1 + B1[col + 1]) * W2[col + 1];
            }
            sum += __shfl_xor_sync(0xffffffffu, sum, 1);
            sum += __shfl_xor_sync(0xffffffffu, sum, 2);
            if ((lane & 3) == 0)
                sred[(warp_m * 64 + fm * 16 + (lane >> 2) + half * 8) * 4 + warp_n] = sum;
        }
    }
    __syncthreads();
    if (tid < 128)
        d_e2[(mBase + tid) * SS + s] =
            sred[tid * 4] + sred[tid * 4 + 1] + sred[tid * 4 + 2] + sred[tid * 4 + 3];
}

// ------------- K10: final softmax-pool -------------
__global__ void k_final(float* __restrict__ out) {
    int b = blockIdx.x, h = threadIdx.x;
    __shared__ float e[SS];
    if (h < SS) e[h] = d_e2[b * SS + h];
    __syncthreads();
    float mx = e[0];
    #pragma unroll
    for (int s = 1; s < SS; s++) mx = fmaxf(mx, e[s]);
    float den = 0.f, w[SS];
    #pragma unroll
    for (int s = 0; s < SS; s++) { w[s] = expf(e[s] - mx); den += w[s]; }
    float inv = 1.f / den;
    float acc = 0.f;
    #pragma unroll
    for (int s = 0; s < SS; s++) {
        size_t o = (size_t)b * SH + s * HH + h;
        acc += w[s] * (__bfloat162float(d_bssh[o]) + __bfloat162float(d_bssl[o]));
    }
    out[b * HH + h] = acc * inv;
}

// ------------- eager materialization -------------
__global__ void k_warm() {}

namespace {
struct EagerInit {
    EagerInit() {
        void* p = nullptr;
        cudaGetSymbolAddress(&p, d_Asp);
        cudaGetSymbolAddress(&p, d_Bsph);
        cudaGetSymbolAddress(&p, d_Bspl);
        cudaGetSymbolAddress(&p, d_bssh);
        cudaGetSymbolAddress(&p, d_bssl);
        cudaFuncAttributes a;
        cudaFuncGetAttributes(&a, k_scores);
        cudaFuncGetAttributes(&a, k_expsel);
        cudaFuncGetAttributes(&a, k_prepAspZ);
        cudaFuncGetAttributes(&a, k_prepBsp);
        cudaFuncGetAttributes(&a, k_wvo);
        cudaFuncGetAttributes(&a, k_M);
        cudaFuncGetAttributes(&a, k_cvec);
        cudaFuncGetAttributes(&a, k_w1c);
        cudaFuncGetAttributes(&a, k_mega);
        cudaFuncGetAttributes(&a, k_final);
        cudaFuncSetAttribute(k_mega,
                             cudaFuncAttributeMaxDynamicSharedMemorySize, SMEM_MEGA);
        k_warm<<<1, 1>>>();
        cudaDeviceSynchronize();
    }
};
EagerInit eager_init_;
}

// ------------- launch -------------
extern "C" void kernel_launch(void* const* d_in, const int* in_sizes, int n_in,
                              void* d_out, int out_size) {
    const float* E    = (const float*)d_in[0];
    const int*   DM   = (const int*)  d_in[2];
    const float* att  = (const float*)d_in[4];
    const float* W1   = (const float*)d_in[8];
    const float* B1   = (const float*)d_in[9];
    const float* W2   = (const float*)d_in[10];
    const float* Wv   = (const float*)d_in[15];
    const float* bv   = (const float*)d_in[16];
    const float* Wo   = (const float*)d_in[17];
    const float* bo   = (const float*)d_in[18];
    const float* LW   = (const float*)d_in[19];
    const float* LB   = (const float*)d_in[20];
    float* out = (float*)d_out;

    k_scores<<<4096, 256>>>(E, att);
    k_expsel<<<SS, 256>>>();
    k_prepAspZ<<<BB, 256>>>(DM);
    k_prepBsp<<<dim3(SS, KCAP / 32), 256>>>(E);
    k_wvo<<<HH, 256>>>(Wo, Wv, bv, bo);
    k_M<<<dim3(SS, 8), 256>>>(LW);
    k_cvec<<<SS, 256>>>(LW, LB);
    k_w1c<<<(HH * HH) / 256, 256>>>(W1);

    k_mega<<<dim3(SS, BB / 128), 256, SMEM_MEGA>>>(B1, W2);
    k_final<<<BB, 256>>>(out);
}

// round 15
// speedup vs baseline: 1.0174x; 1.0174x over previous
#include <cuda_runtime.h>
#include <cuda_bf16.h>
#include <cstdint>
#include <cstddef>

#define BB 2048
#define SS 8
#define NN 4096
#define HH 256
#define SH 2048
#define KCAP 512
#define TAU 9.094947017729282e-13f   // 2^-40

// ------------- static scratch -------------
__device__ float d_g[SS * NN];
__device__ float d_Zinv[BB * SS];
__device__ float d_Wvo[HH * HH];
__device__ float d_bconst[HH];
__device__ float d_cvec[SS * HH];
__device__ float d_e2[BB * SS];
__device__ int   d_idx[SS * KCAP];
__device__ int   d_cnt[SS];
__device__ __align__(128) __nv_bfloat16 d_Asp[(size_t)SS * BB * KCAP];   // 16MB
__device__ __align__(128) __nv_bfloat16 d_Bsph[(size_t)SS * HH * KCAP]; // 2MB
__device__ __align__(128) __nv_bfloat16 d_Bspl[(size_t)SS * HH * KCAP]; // 2MB
__device__ __align__(128) __nv_bfloat16 d_Mth[SS * HH * HH];
__device__ __align__(128) __nv_bfloat16 d_Mtl[SS * HH * HH];
__device__ __align__(128) __nv_bfloat16 d_W1h[HH * HH];
__device__ __align__(128) __nv_bfloat16 d_W1l[HH * HH];
__device__ __align__(128) __nv_bfloat16 d_bssh[(size_t)BB * SH];   // 8MB
__device__ __align__(128) __nv_bfloat16 d_bssl[(size_t)BB * SH];   // 8MB

__device__ __forceinline__ uint32_t smem_u32(const void* p) {
    uint32_t a;
    asm("{ .reg .u64 t; cvta.to.shared.u64 t, %1; cvt.u32.u64 %0, t; }" : "=r"(a) : "l"(p));
    return a;
}

#define LDMX4(r, addr)                                                         \
    asm volatile("ldmatrix.sync.aligned.m8n8.x4.shared.b16 {%0,%1,%2,%3}, [%4];" \
        : "=r"((r)[0]), "=r"((r)[1]), "=r"((r)[2]), "=r"((r)[3]) : "r"(addr))

#define MMA16816(d, a, b0, b1)                                                 \
    asm volatile("mma.sync.aligned.m16n8k16.row.col.f32.bf16.bf16.f32 "        \
        "{%0,%1,%2,%3},{%4,%5,%6,%7},{%8,%9},{%0,%1,%2,%3};"                   \
        : "+f"((d)[0]), "+f"((d)[1]), "+f"((d)[2]), "+f"((d)[3])               \
        : "r"((a)[0]), "r"((a)[1]), "r"((a)[2]), "r"((a)[3]), "r"(b0), "r"(b1))

#define CP16(saddr, gptr)                                                      \
    asm volatile("cp.async.cg.shared.global [%0], [%1], 16;"                   \
        :: "r"(saddr), "l"(gptr) : "memory")

__device__ __forceinline__ uint32_t pack_hi(float a, float b) {
    __nv_bfloat162 p;
    p.x = __float2bfloat16(a); p.y = __float2bfloat16(b);
    return *(uint32_t*)&p;
}
__device__ __forceinline__ uint32_t pack_lo(float a, float b) {
    __nv_bfloat162 p;
    p.x = __float2bfloat16(a - __bfloat162float(__float2bfloat16(a)));
    p.y = __float2bfloat16(b - __bfloat162float(__float2bfloat16(b)));
    return *(uint32_t*)&p;
}

// ------------- K1: scores -------------
__global__ void k_scores(const float* __restrict__ E, const float* __restrict__ att) {
    __shared__ float satt[HH];
    int tid = threadIdx.x;
    satt[tid] = att[tid];
    __syncthreads();
    int w = tid >> 5, lane = tid & 31;
    int s = blockIdx.x >> 9;
    int n = ((blockIdx.x & 511) << 3) + w;
    const float* e = E + ((size_t)s * NN + n) * HH + lane * 8;
    const float* a = satt + lane * 8;
    float4 v0 = *(const float4*)e, v1 = *(const float4*)(e + 4);
    float4 a0 = *(const float4*)a, a1 = *(const float4*)(a + 4);
    float acc = v0.x*a0.x + v0.y*a0.y + v0.z*a0.z + v0.w*a0.w
              + v1.x*a1.x + v1.y*a1.y + v1.z*a1.z + v1.w*a1.w;
    #pragma unroll
    for (int o = 16; o; o >>= 1) acc += __shfl_xor_sync(0xffffffffu, acc, o);
    if (lane == 0) d_g[s * NN + n] = acc;
}

// ------------- K2: max + exp + select (one CTA per s) -------------
__global__ void k_expsel() {
    int s = blockIdx.x, tid = threadIdx.x;
    int lane = tid & 31, wid = tid >> 5;
    __shared__ float wmax[8];
    __shared__ int wtot[8], woff[8], stot;
    int base = tid * 16;
    float sc[16];
    float mx = -1e30f;
    #pragma unroll
    for (int j = 0; j < 16; j++) {
        sc[j] = d_g[s * NN + base + j];
        mx = fmaxf(mx, sc[j]);
    }
    #pragma unroll
    for (int o = 16; o; o >>= 1) mx = fmaxf(mx, __shfl_xor_sync(0xffffffffu, mx, o));
    if (lane == 0) wmax[wid] = mx;
    __syncthreads();
    float gmx = wmax[0];
    #pragma unroll
    for (int i = 1; i < 8; i++) gmx = fmaxf(gmx, wmax[i]);

    float gv[16];
    int c = 0;
    #pragma unroll
    for (int j = 0; j < 16; j++) {
        gv[j] = expf(sc[j] - gmx);
        d_g[s * NN + base + j] = gv[j];
        c += (gv[j] >= TAU) ? 1 : 0;
    }
    int v = c;
    #pragma unroll
    for (int o = 1; o < 32; o <<= 1) {
        int t = __shfl_up_sync(0xffffffffu, v, o);
        if (lane >= o) v += t;
    }
    if (lane == 31) wtot[wid] = v;
    __syncthreads();
    if (tid == 0) {
        int a = 0;
        #pragma unroll
        for (int i = 0; i < 8; i++) { woff[i] = a; a += wtot[i]; }
        stot = a;
    }
    __syncthreads();
    int o = woff[wid] + v - c;
    #pragma unroll
    for (int j = 0; j < 16; j++) {
        if (gv[j] >= TAU) {
            if (o < KCAP) d_idx[s * KCAP + o] = base + j;
            o++;
        }
    }
    int total = stot < KCAP ? stot : KCAP;
    if (tid == 0) d_cnt[s] = total;
    for (int k = total + tid; k < KCAP; k += 256) d_idx[s * KCAP + k] = 0;
}

// ------------- K3: Asp[s][b][k] = bf16(mask[b, idx_k]) + SPARSE Zinv --------
// One CTA = (s, 8 b-rows); warp w owns b. g_sel/idx staged in smem. (R13 ver.)
__global__ void k_prepAspZ(const int* __restrict__ DM) {
    int s = blockIdx.x;
    int w = threadIdx.x >> 5, lane = threadIdx.x & 31;
    int b = blockIdx.y * 8 + w;
    __shared__ float sg[KCAP];
    __shared__ int sidx[KCAP];
    int cnt = d_cnt[s];
    int lim = (cnt + 31) & ~31;
    for (int k = threadIdx.x; k < lim; k += 256) {
        int n = d_idx[s * KCAP + k];
        sidx[k] = n;
        sg[k] = (k < cnt) ? d_g[s * NN + n] : 0.f;
    }
    __syncthreads();
    float z = 0.f;
    for (int k = lane; k < lim; k += 32) {
        float v = (k < cnt) ? (float)DM[(size_t)b * NN + sidx[k]] : 0.f;
        d_Asp[((size_t)s * BB + b) * KCAP + k] = __float2bfloat16(v);
        z += v * sg[k];
    }
    #pragma unroll
    for (int o = 16; o; o >>= 1) z += __shfl_xor_sync(0xffffffffu, z, o);
    if (lane == 0) d_Zinv[b * SS + s] = 1.f / z;
}

// ------------- K4: Bsp[s][h][k] = hi/lo of g*E at idx_k -------------
__global__ void k_prepBsp(const float* __restrict__ E) {
    int s = blockIdx.x, kt = blockIdx.y, tid = threadIdx.x;
    int cnt = d_cnt[s];
    if (kt * 32 >= ((cnt + 31) & ~31)) return;
    __shared__ float tile[32][257];
    for (int r = 0; r < 32; r++) {
        int k = kt * 32 + r;
        int n = d_idx[s * KCAP + k];
        float gv = (k < cnt) ? d_g[s * NN + n] : 0.f;
        tile[r][tid] = gv * E[((size_t)s * NN + n) * HH + tid];
    }
    __syncthreads();
    int h = tid;
    #pragma unroll
    for (int r = 0; r < 32; r += 2) {
        size_t o = ((size_t)s * HH + h) * KCAP + kt * 32 + r;
        *(uint32_t*)(d_Bsph + o) = pack_hi(tile[r][h], tile[r + 1][h]);
        *(uint32_t*)(d_Bspl + o) = pack_lo(tile[r][h], tile[r + 1][h]);
    }
}

// ------------- K5: Wvo / bconst -------------
__global__ void k_wvo(const float* __restrict__ Wo, const float* __restrict__ Wv,
                      const float* __restrict__ bv, const float* __restrict__ bo) {
    int g = blockIdx.x, tid = threadIdx.x;
    __shared__ float srow[HH];
    __shared__ float red[HH];
    srow[tid] = Wo[g * HH + tid];
    __syncthreads();
    float acc = 0.f;
    #pragma unroll 4
    for (int k = 0; k < HH; k++) acc += srow[k] * Wv[k * HH + tid];
    d_Wvo[g * HH + tid] = acc;
    red[tid] = srow[tid] * bv[tid];
    __syncthreads();
    for (int o = 128; o; o >>= 1) {
        if (tid < o) red[tid] += red[tid + o];
        __syncthreads();
    }
    if (tid == 0) d_bconst[g] = red[0] + bo[g];
}

// ------------- K6: Mtb[s][g][h] = ((I+L_s)@Wvo)[g,h], bf16 hi/lo -------------
__global__ void k_M(const float* __restrict__ LW) {
    int s = blockIdx.x, gt = blockIdx.y;
    int h = threadIdx.x;
    __shared__ float sL[32][HH];
    for (int g = 0; g < 32; g++)
        sL[g][h] = LW[((size_t)s * HH + gt * 32 + g) * HH + h];
    __syncthreads();
    float acc[32];
    #pragma unroll
    for (int g = 0; g < 32; g++) acc[g] = d_Wvo[(gt * 32 + g) * HH + h];
    #pragma unroll 4
    for (int k = 0; k < HH; k++) {
        float wv = d_Wvo[k * HH + h];
        #pragma unroll
        for (int g = 0; g < 32; g++) acc[g] += sL[g][k] * wv;
    }
    for (int g = 0; g < 32; g++) {
        float v = acc[g];
        __nv_bfloat16 hi = __float2bfloat16(v);
        __nv_bfloat16 lo = __float2bfloat16(v - __bfloat162float(hi));
        size_t o = (size_t)(s * HH + gt * 32 + g) * HH + h;
        d_Mth[o] = hi;
        d_Mtl[o] = lo;
    }
}

// ------------- K7: cvec -------------
__global__ void k_cvec(const float* __restrict__ LW, const float* __restrict__ LB) {
    int s = blockIdx.x, g = threadIdx.x;
    __shared__ float sb[HH];
    sb[g] = d_bconst[g];
    __syncthreads();
    float acc = 0.f;
    #pragma unroll 4
    for (int k = 0; k < HH; k++) acc += LW[((size_t)s * HH + g) * HH + k] * sb[k];
    d_cvec[s * HH + g] = d_bconst[g] + acc + LB[s * HH + g];
}

// ------------- K8: W1 -> bf16 hi/lo -------------
__global__ void k_w1c(const float* __restrict__ W1) {
    int i = blockIdx.x * 256 + threadIdx.x;
    float v = W1[i];
    __nv_bfloat16 hi = __float2bfloat16(v);
    d_W1h[i] = hi;
    d_W1l[i] = __float2bfloat16(v - __bfloat162float(hi));
}

// ====================================================================
// MEGA kernel: CTA = (s, 128 b-rows). Grid (8, 16).
// Phase 1: sparse numerator GEMM -> scaled bsym hi/lo into smem planes
// Phase 2: bsym @ Mt^T (3-pass) + cvec -> bssh/bssl global + planes
// Phase 3: bss @ W1^T (3-pass) -> tanh-reduce -> d_e2
// Depth-1 double buffer; epilogue 2 recomputes packs (no reg staging).
// ====================================================================
#define BK 32
#define STG 40960
#define PSTR 528
#define PLH 81920
#define PLL 149504
#define SMEM_MEGA 217088

__global__ __launch_bounds__(256, 1) void k_mega(
    const float* __restrict__ B1, const float* __restrict__ W2)
{
    extern __shared__ char smem[];
    const int tid = threadIdx.x, wid = tid >> 5, lane = tid & 31;
    const int warp_m = wid & 1, warp_n = wid >> 1;
    const int s = blockIdx.x, mBase = blockIdx.y * 128;
    const uint32_t sb = smem_u32(smem);

    const int cRow = tid >> 2, cSeg = tid & 3;
    const uint32_t aOfs1 = (warp_m * 64 + (lane & 15)) * 80 + (lane >> 4) * 16;
    const uint32_t bRowF = warp_n * 64 + (lane & 7) + ((lane >> 4) << 3);
    const uint32_t bFr = bRowF * 80 + ((lane >> 3) & 1) * 16;
    const uint32_t aPRow = (warp_m * 64 + (lane & 15)) * PSTR + (lane >> 4) * 16;

    float acc[4][8][4];

    // =================== PHASE 1: sparse numerator ===================
    {
        const __nv_bfloat16* aC = d_Asp  + ((size_t)s * BB + mBase) * KCAP;
        const __nv_bfloat16* bH = d_Bsph + (size_t)s * HH * KCAP;
        const __nv_bfloat16* bL = d_Bspl + (size_t)s * HH * KCAP;
        const int cnt = d_cnt[s];
        const int nch = (cnt + 31) >> 5;
        const int NT = 2 * nch;

        #pragma unroll
        for (int fm = 0; fm < 4; fm++)
            #pragma unroll
            for (int fn = 0; fn < 8; fn++)
                #pragma unroll
                for (int q = 0; q < 4; q++) acc[fm][fn][q] = 0.f;

        auto issue1 = [&](int kt) {
            uint32_t s0 = sb + (kt & 1) * STG;
            int kk = (kt < nch) ? kt : kt - nch;
            const __nv_bfloat16* bp = (kt < nch) ? bH : bL;
            #pragma unroll
            for (int i = 0; i < 2; i++) {
                int row = cRow + i * 64;
                CP16(s0 + row * 80 + cSeg * 16, aC + (size_t)row * KCAP + kk * BK + cSeg * 8);
            }
            #pragma unroll
            for (int i = 0; i < 4; i++) {
                int row = cRow + i * 64;
                CP16(s0 + 10240 + row * 80 + cSeg * 16, bp + (size_t)row * KCAP + kk * BK + cSeg * 8);
            }
            asm volatile("cp.async.commit_group;" ::: "memory");
        };

        issue1(0);
        for (int kt = 0; kt < NT; kt++) {
            asm volatile("cp.async.wait_group 0;" ::: "memory");
            __syncthreads();
            if (kt + 1 < NT) issue1(kt + 1);
            uint32_t sA = sb + (kt & 1) * STG;
            #pragma unroll
            for (int ks = 0; ks < 2; ks++) {
                uint32_t aF[4][4], bF[4][4];
                #pragma unroll
                for (int fm = 0; fm < 4; fm++)
                    LDMX4(aF[fm], sA + aOfs1 + fm * (16 * 80) + ks * 32);
                #pragma unroll
                for (int fb = 0; fb < 4; fb++)
                    LDMX4(bF[fb], sA + 10240 + bFr + fb * (16 * 80) + ks * 32);
                #pragma unroll
                for (int fm = 0; fm < 4; fm++)
                    #pragma unroll
                    for (int fn = 0; fn < 8; fn++)
                        MMA16816(acc[fm][fn], aF[fm],
                                 bF[fn >> 1][(fn & 1) * 2], bF[fn >> 1][(fn & 1) * 2 + 1]);
            }
        }

        // epilogue 1: scale by Zinv, write hi/lo into smem planes
        __syncthreads();
        #pragma unroll
        for (int fm = 0; fm < 4; fm++) {
            int rl = warp_m * 64 + fm * 16 + (lane >> 2);
            float zi0 = d_Zinv[(mBase + rl) * SS + s];
            float zi1 = d_Zinv[(mBase + rl + 8) * SS + s];
            #pragma unroll
            for (int fn = 0; fn < 8; fn++) {
                int col = warp_n * 64 + fn * 8 + (lane & 3) * 2;
                float v00 = acc[fm][fn][0] * zi0, v01 = acc[fm][fn][1] * zi0;
                float v10 = acc[fm][fn][2] * zi1, v11 = acc[fm][fn][3] * zi1;
                *(uint32_t*)(smem + PLH + rl * PSTR + col * 2)       = pack_hi(v00, v01);
                *(uint32_t*)(smem + PLL + rl * PSTR + col * 2)       = pack_lo(v00, v01);
                *(uint32_t*)(smem + PLH + (rl + 8) * PSTR + col * 2) = pack_hi(v10, v11);
                *(uint32_t*)(smem + PLL + (rl + 8) * PSTR + col * 2) = pack_lo(v10, v11);
            }
        }
    }
    __syncthreads();

    // =================== PHASE 2 & 3 shared mainloop ===================
    auto gemm_planes = [&](const __nv_bfloat16* Bh, const __nv_bfloat16* Bl) {
        #pragma unroll
        for (int fm = 0; fm < 4; fm++)
            #pragma unroll
            for (int fn = 0; fn < 8; fn++)
                #pragma unroll
                for (int q = 0; q < 4; q++) acc[fm][fn][q] = 0.f;

        auto issue2 = [&](int kt) {
            uint32_t s0 = sb + (kt & 1) * STG;
            #pragma unroll
            for (int i = 0; i < 4; i++) {
                int row = cRow + i * 64;
                size_t go = (size_t)row * HH + kt * BK + cSeg * 8;
                CP16(s0 + row * 80 + cSeg * 16, Bh + go);
                CP16(s0 + 20480 + row * 80 + cSeg * 16, Bl + go);
            }
            asm volatile("cp.async.commit_group;" ::: "memory");
        };

        const int NT = HH / BK;   // 8
        issue2(0);
        for (int kt = 0; kt < NT; kt++) {
            asm volatile("cp.async.wait_group 0;" ::: "memory");
            __syncthreads();
            if (kt + 1 < NT) issue2(kt + 1);
            uint32_t sA = sb + (kt & 1) * STG;
            #pragma unroll
            for (int ks = 0; ks < 2; ks++) {
                uint32_t aH[4][4], aL[4][4], bF[4][4];
                uint32_t aCol = kt * 64 + ks * 32;
                #pragma unroll
                for (int fm = 0; fm < 4; fm++) {
                    LDMX4(aH[fm], sb + PLH + aPRow + fm * (16 * PSTR) + aCol);
                    LDMX4(aL[fm], sb + PLL + aPRow + fm * (16 * PSTR) + aCol);
                }
                #pragma unroll
                for (int fb = 0; fb < 4; fb++)
                    LDMX4(bF[fb], sA + bFr + fb * (16 * 80) + ks * 32);
                #pragma unroll
                for (int fm = 0; fm < 4; fm++)
                    #pragma unroll
                    for (int fn = 0; fn < 8; fn++) {
                        MMA16816(acc[fm][fn], aH[fm],
                                 bF[fn >> 1][(fn & 1) * 2], bF[fn >> 1][(fn & 1) * 2 + 1]);
                        MMA16816(acc[fm][fn], aL[fm],
                                 bF[fn >> 1][(fn & 1) * 2], bF[fn >> 1][(fn & 1) * 2 + 1]);
                    }
                #pragma unroll
                for (int fb = 0; fb < 4; fb++)
                    LDMX4(bF[fb], sA + 20480 + bFr + fb * (16 * 80) + ks * 32);
                #pragma unroll
                for (int fm = 0; fm < 4; fm++)
                    #pragma unroll
                    for (int fn = 0; fn < 8; fn++)
                        MMA16816(acc[fm][fn], aH[fm],
                                 bF[fn >> 1][(fn & 1) * 2], bF[fn >> 1][(fn & 1) * 2 + 1]);
            }
        }
    };

    // =================== PHASE 2: bss ===================
    gemm_planes(d_Mth + (size_t)s * HH * HH, d_Mtl + (size_t)s * HH * HH);

    // epilogue 2a: +cvec, write bssh/bssl global (no plane staging regs)
    #pragma unroll
    for (int fm = 0; fm < 4; fm++) {
        int rl = warp_m * 64 + fm * 16 + (lane >> 2);
        #pragma unroll
        for (int fn = 0; fn < 8; fn++) {
            int col = warp_n * 64 + fn * 8 + (lane & 3) * 2;
            float c0 = d_cvec[s * HH + col], c1 = d_cvec[s * HH + col + 1];
            float v00 = acc[fm][fn][0] + c0, v01 = acc[fm][fn][1] + c1;
            float v10 = acc[fm][fn][2] + c0, v11 = acc[fm][fn][3] + c1;
            size_t o0 = (size_t)(mBase + rl) * SH + s * HH + col;
            size_t o1 = (size_t)(mBase + rl + 8) * SH + s * HH + col;
            *(uint32_t*)(d_bssh + o0) = pack_hi(v00, v01);
            *(uint32_t*)(d_bssl + o0) = pack_lo(v00, v01);
            *(uint32_t*)(d_bssh + o1) = pack_hi(v10, v11);
            *(uint32_t*)(d_bssl + o1) = pack_lo(v10, v11);
        }
    }
    __syncthreads();   // all reads of old planes done
    // epilogue 2b: recompute packs from acc (still live), write planes
    #pragma unroll
    for (int fm = 0; fm < 4; fm++) {
        int rl = warp_m * 64 + fm * 16 + (lane >> 2);
        #pragma unroll
        for (int fn = 0; fn < 8; fn++) {
            int col = warp_n * 64 + fn * 8 + (lane & 3) * 2;
            float c0 = d_cvec[s * HH + col], c1 = d_cvec[s * HH + col + 1];
            float v00 = acc[fm][fn][0] + c0, v01 = acc[fm][fn][1] + c1;
            float v10 = acc[fm][fn][2] + c0, v11 = acc[fm][fn][3] + c1;
            *(uint32_t*)(smem + PLH + rl * PSTR + col * 2)       = pack_hi(v00, v01);
            *(uint32_t*)(smem + PLL + rl * PSTR + col * 2)       = pack_lo(v00, v01);
            *(uint32_t*)(smem + PLH + (rl + 8) * PSTR + col * 2) = pack_hi(v10, v11);
            *(uint32_t*)(smem + PLL + (rl + 8) * PSTR + col * 2) = pack_lo(v10, v11);
        }
    }
    __syncthreads();

    // =================== PHASE 3: e2 ===================
    gemm_planes(d_W1h, d_W1l);

    // epilogue 3: tanh-reduce
    __syncthreads();  // stage region now free for sred
    float* sred = (float*)smem;   // [128][4]
    #pragma unroll
    for (int fm = 0; fm < 4; fm++) {
        #pragma unroll
        for (int half = 0; half < 2; half++) {
            float sum = 0.f;
            #pragma unroll
            for (int fn = 0; fn < 8; fn++) {
                int col = warp_n * 64 + fn * 8 + (lane & 3) * 2;
                float v0 = acc[fm][fn][half * 2 + 0];
                float v1 = acc[fm][fn][half * 2 + 1];
                sum += tanhf(v0 + B1[col]) * W2[col]
                     + tanhf(v1 + B1[col + 1]) * W2[col + 1];
            }
            sum += __shfl_xor_sync(0xffffffffu, sum, 1);
            sum += __shfl_xor_sync(0xffffffffu, sum, 2);
            if ((lane & 3) == 0)
                sred[(warp_m * 64 + fm * 16 + (lane >> 2) + half * 8) * 4 + warp_n] = sum;
        }
    }
    __syncthreads();
    if (tid < 128)
        d_e2[(mBase + tid) * SS + s] =
            sred[tid * 4] + sred[tid * 4 + 1] + sred[tid * 4 + 2] + sred[tid * 4 + 3];
}

// ------------- K10: final softmax-pool -------------
__global__ void k_final(float* __restrict__ out) {
    int b = blockIdx.x, h = threadIdx.x;
    __shared__ float e[SS];
    if (h < SS) e[h] = d_e2[b * SS + h];
    __syncthreads();
    float mx = e[0];
    #pragma unroll
    for (int s = 1; s < SS; s++) mx = fmaxf(mx, e[s]);
    float den = 0.f, w[SS];
    #pragma unroll
    for (int s = 0; s < SS; s++) { w[s] = expf(e[s] - mx); den += w[s]; }
    float inv = 1.f / den;
    float acc = 0.f;
    #pragma unroll
    for (int s = 0; s < SS; s++) {
        size_t o = (size_t)b * SH + s * HH + h;
        acc += w[s] * (__bfloat162float(d_bssh[o]) + __bfloat162float(d_bssl[o]));
    }
    out[b * HH + h] = acc * inv;
}

// ------------- eager materialization -------------
__global__ void k_warm() {}

namespace {
struct EagerInit {
    EagerInit() {
        void* p = nullptr;
        cudaGetSymbolAddress(&p, d_Asp);
        cudaGetSymbolAddress(&p, d_Bsph);
        cudaGetSymbolAddress(&p, d_Bspl);
        cudaGetSymbolAddress(&p, d_bssh);
        cudaGetSymbolAddress(&p, d_bssl);
        cudaFuncAttributes a;
        cudaFuncGetAttributes(&a, k_scores);
        cudaFuncGetAttributes(&a, k_expsel);
        cudaFuncGetAttributes(&a, k_prepAspZ);
        cudaFuncGetAttributes(&a, k_prepBsp);
        cudaFuncGetAttributes(&a, k_wvo);
        cudaFuncGetAttributes(&a, k_M);
        cudaFuncGetAttributes(&a, k_cvec);
        cudaFuncGetAttributes(&a, k_w1c);
        cudaFuncGetAttributes(&a, k_mega);
        cudaFuncGetAttributes(&a, k_final);
        cudaFuncSetAttribute(k_mega,
                             cudaFuncAttributeMaxDynamicSharedMemorySize, SMEM_MEGA);
        k_warm<<<1, 1>>>();
        cudaDeviceSynchronize();
    }
};
EagerInit eager_init_;
}

// ------------- launch -------------
extern "C" void kernel_launch(void* const* d_in, const int* in_sizes, int n_in,
                              void* d_out, int out_size) {
    const float* E    = (const float*)d_in[0];
    const int*   DM   = (const int*)  d_in[2];
    const float* att  = (const float*)d_in[4];
    const float* W1   = (const float*)d_in[8];
    const float* B1   = (const float*)d_in[9];
    const float* W2   = (const float*)d_in[10];
    const float* Wv   = (const float*)d_in[15];
    const float* bv   = (const float*)d_in[16];
    const float* Wo   = (const float*)d_in[17];
    const float* bo   = (const float*)d_in[18];
    const float* LW   = (const float*)d_in[19];
    const float* LB   = (const float*)d_in[20];
    float* out = (float*)d_out;

    k_scores<<<4096, 256>>>(E, att);
    k_expsel<<<SS, 256>>>();
    k_prepAspZ<<<dim3(SS, BB / 8), 256>>>(DM);
    k_prepBsp<<<dim3(SS, KCAP / 32), 256>>>(E);
    k_wvo<<<HH, 256>>>(Wo, Wv, bv, bo);
    k_M<<<dim3(SS, 8), 256>>>(LW);
    k_cvec<<<SS, 256>>>(LW, LB);
    k_w1c<<<(HH * HH) / 256, 256>>>(W1);

    k_mega<<<dim3(SS, BB / 128), 256, SMEM_MEGA>>>(B1, W2);
    k_final<<<BB, 256>>>(out);
}